// round 1
// baseline (speedup 1.0000x reference)
#include <cuda_runtime.h>
#include <cuda_bf16.h>

#define NN 50000
#define EE 1600000
#define DD 32
#define NLAYERS 8
#define TOPK 8

// ---------------- device scratch (static, no allocations) ----------------
__device__ float g_h [NN*DD];
__device__ float g_hi[NN*DD];
__device__ float g_hj[NN*DD];
__device__ float g_hn[NN*DD];
__device__ float g_e [EE*DD];
__device__ float g_f [EE*DD];
__device__ float g_logits[EE];
__device__ int   g_srcS[EE];
__device__ int   g_dstS[EE];
__device__ int   g_perm[EE];
__device__ int   g_hist[NN];
__device__ int   g_row [NN+1];
__device__ int   g_cursor[NN];
__device__ float g_rowmax[NN];

// ---------------- CSR build (counting sort by dst) ----------------
__global__ void k_zero_hist() {
    int i = blockIdx.x * blockDim.x + threadIdx.x;
    if (i < NN) g_hist[i] = 0;
}

__global__ void k_hist(const int* __restrict__ dst) {
    int i = blockIdx.x * blockDim.x + threadIdx.x;
    if (i < EE) atomicAdd(&g_hist[dst[i]], 1);
}

__global__ void k_scan() {
    __shared__ int sm[1024];
    int t = threadIdx.x;
    const int CH = (NN + 1023) / 1024;
    int b0 = t * CH;
    int b1 = min(b0 + CH, NN);
    int sum = 0;
    for (int i = b0; i < b1; i++) sum += g_hist[i];
    sm[t] = sum;
    __syncthreads();
    // Hillis-Steele inclusive scan
    for (int off = 1; off < 1024; off <<= 1) {
        int v = (t >= off) ? sm[t - off] : 0;
        __syncthreads();
        sm[t] += v;
        __syncthreads();
    }
    int pre = sm[t] - sum;  // exclusive prefix
    for (int i = b0; i < b1; i++) {
        g_row[i] = pre;
        g_cursor[i] = pre;
        pre += g_hist[i];
    }
    if (t == 1023) g_row[NN] = sm[1023];
}

__global__ void k_scatter(const int* __restrict__ dst) {
    int i = blockIdx.x * blockDim.x + threadIdx.x;
    if (i < EE) {
        int d = dst[i];
        int p = atomicAdd(&g_cursor[d], 1);
        g_perm[p] = i;
    }
}

__global__ void k_gather(const int* __restrict__ src, const int* __restrict__ dst,
                         const int* __restrict__ e_tok, const float* __restrict__ e_emb) {
    int i = blockIdx.x * blockDim.x + threadIdx.x;
    if (i >= EE) return;
    int o = g_perm[i];
    g_srcS[i] = src[o];
    g_dstS[i] = dst[o];
    int tok = e_tok[o];
    const float4* eb = (const float4*)e_emb;
    float4* eo = (float4*)g_e;
#pragma unroll
    for (int q = 0; q < 8; q++) eo[(size_t)i * 8 + q] = eb[tok * 8 + q];
}

__global__ void k_hinit(const int* __restrict__ h_tok, const float* __restrict__ tok_emb) {
    int idx = blockIdx.x * blockDim.x + threadIdx.x;
    if (idx >= NN * DD) return;
    int n = idx >> 5, d = idx & 31;
    float v = tok_emb[h_tok[n] * DD + d];
    g_h[idx] = fmaxf(v, 0.f);
}

// ---------------- per-layer kernels ----------------
// node projections: hi = h@Wni + b, hj = h@Wnj, hn = h@Wnode. Warp per node.
__global__ void k_proj(const float* __restrict__ Wni, const float* __restrict__ Wnj,
                       const float* __restrict__ Wn, const float* __restrict__ b) {
    __shared__ float wi[32][32], wj[32][32], wn[32][32];
    __shared__ float bs[32];
    int tid = threadIdx.x;
    for (int i = tid; i < 1024; i += 256) {
        wi[i >> 5][i & 31] = Wni[i];
        wj[i >> 5][i & 31] = Wnj[i];
        wn[i >> 5][i & 31] = Wn[i];
    }
    if (tid < 32) bs[tid] = b[tid];
    __syncthreads();
    int node = blockIdx.x * 8 + (tid >> 5);
    int lane = tid & 31;
    if (node >= NN) return;
    float hv = g_h[node * DD + lane];
    float ai = bs[lane], aj = 0.f, an = 0.f;
#pragma unroll
    for (int k = 0; k < 32; k++) {
        float hk = __shfl_sync(0xffffffffu, hv, k);
        ai += hk * wi[k][lane];
        aj += hk * wj[k][lane];
        an += hk * wn[k][lane];
    }
    g_hi[node * DD + lane] = ai;
    g_hj[node * DD + lane] = aj;
    g_hn[node * DD + lane] = an;
}

// edge kernel: f = lrelu(hi[src] + hj[dst] + e@Wfij); logit = dot(f, attn)
__global__ void k_edge(const float* __restrict__ Wf, const float* __restrict__ attn, int swap) {
    __shared__ float Ws[32][32];
    __shared__ float As[32];
    int tid = threadIdx.x;
    for (int i = tid; i < 1024; i += 256) Ws[i >> 5][i & 31] = Wf[i];
    if (tid < 32) As[tid] = attn[tid];
    __syncthreads();
    int edge = blockIdx.x * 256 + tid;
    if (edge >= EE) return;
    const float4* ein = (const float4*)(swap ? g_f : g_e);
    float4* fout = (float4*)(swap ? g_e : g_f);
    int s = g_srcS[edge];
    int dn = g_dstS[edge];
    const float4* hi4 = (const float4*)g_hi;
    const float4* hj4 = (const float4*)g_hj;
    float acc[32];
#pragma unroll
    for (int q = 0; q < 8; q++) {
        float4 a = hi4[s * 8 + q];
        float4 b = hj4[dn * 8 + q];
        acc[4 * q + 0] = a.x + b.x;
        acc[4 * q + 1] = a.y + b.y;
        acc[4 * q + 2] = a.z + b.z;
        acc[4 * q + 3] = a.w + b.w;
    }
#pragma unroll
    for (int q = 0; q < 8; q++) {
        float4 ev = ein[(size_t)edge * 8 + q];
#pragma unroll
        for (int j = 0; j < 32; j++) {
            acc[j] += ev.x * Ws[4 * q + 0][j] + ev.y * Ws[4 * q + 1][j]
                    + ev.z * Ws[4 * q + 2][j] + ev.w * Ws[4 * q + 3][j];
        }
    }
    float logit = 0.f;
#pragma unroll
    for (int j = 0; j < 32; j++) {
        float v = acc[j];
        v = (v > 0.f) ? v : 0.01f * v;
        acc[j] = v;
        logit += v * As[j];
    }
#pragma unroll
    for (int q = 0; q < 8; q++) {
        fout[(size_t)edge * 8 + q] =
            make_float4(acc[4 * q + 0], acc[4 * q + 1], acc[4 * q + 2], acc[4 * q + 3]);
    }
    g_logits[edge] = logit;
}

// aggregation: edge softmax over incoming edges + weighted sum of hn[src], relu.
__global__ void k_agg() {
    int node = (blockIdx.x * blockDim.x + threadIdx.x) >> 5;
    int lane = threadIdx.x & 31;
    if (node >= NN) return;
    int beg = g_row[node], end = g_row[node + 1];
    float m = -1e30f;
    for (int i = beg + lane; i < end; i += 32) m = fmaxf(m, g_logits[i]);
#pragma unroll
    for (int o = 16; o; o >>= 1) m = fmaxf(m, __shfl_xor_sync(0xffffffffu, m, o));
    float s = 0.f, acc = 0.f;
    for (int i = beg; i < end; i++) {
        float w = __expf(g_logits[i] - m);
        s += w;
        acc += w * g_hn[g_srcS[i] * DD + lane];
    }
    float hv = (end > beg) ? (acc / s) : 0.f;
    g_h[node * DD + lane] = fmaxf(hv, 0.f);
}

// ---------------- SortPooling + MLP head ----------------
__global__ void k_rowmax() {
    int node = (blockIdx.x * blockDim.x + threadIdx.x) >> 5;
    int lane = threadIdx.x & 31;
    if (node >= NN) return;
    float v = g_h[node * DD + lane];
#pragma unroll
    for (int o = 16; o; o >>= 1) v = fmaxf(v, __shfl_xor_sync(0xffffffffu, v, o));
    if (lane == 0) g_rowmax[node] = v;
}

__global__ void k_head(const float* __restrict__ Wlin, const float* __restrict__ blin,
                       const float* __restrict__ W1, const float* __restrict__ b1,
                       const float* __restrict__ W2, const float* __restrict__ b2,
                       const float* __restrict__ Wc, const float* __restrict__ bc,
                       float* __restrict__ out) {
    __shared__ float sv[256];
    __shared__ int si[256];
    __shared__ int picked[TOPK];
    __shared__ float xs[TOPK * DD];
    __shared__ float y1[32], y2[32], y3[32];
    int tid = threadIdx.x;

    // sequential top-8 by rowmax (descending, smaller index on ties)
    for (int t = 0; t < TOPK; t++) {
        float best = -1e30f;
        int bidx = 0x7fffffff;
        for (int i = tid; i < NN; i += 256) {
            bool skip = false;
            for (int p = 0; p < t; p++)
                if (picked[p] == i) skip = true;
            if (skip) continue;
            float v = g_rowmax[i];
            if (v > best || (v == best && i < bidx)) { best = v; bidx = i; }
        }
        sv[tid] = best;
        si[tid] = bidx;
        __syncthreads();
        for (int off = 128; off; off >>= 1) {
            if (tid < off) {
                float v2 = sv[tid + off];
                int i2 = si[tid + off];
                if (v2 > sv[tid] || (v2 == sv[tid] && i2 < si[tid])) {
                    sv[tid] = v2;
                    si[tid] = i2;
                }
            }
            __syncthreads();
        }
        if (tid == 0) picked[t] = si[0];
        __syncthreads();
    }

    // sort each picked node's features ascending
    if (tid < TOPK) {
        float r[32];
        int n = picked[tid];
        for (int d = 0; d < 32; d++) r[d] = g_h[n * DD + d];
        for (int a = 1; a < 32; a++) {
            float key = r[a];
            int b = a - 1;
            while (b >= 0 && r[b] > key) { r[b + 1] = r[b]; b--; }
            r[b + 1] = key;
        }
        for (int d = 0; d < 32; d++) xs[tid * 32 + d] = r[d];
    }
    __syncthreads();

    // MLP: 256 -> 32 -> 32 -> 32 -> 2
    if (tid < 32) {
        float a = blin[tid];
        for (int i = 0; i < 256; i++) a += xs[i] * Wlin[i * 32 + tid];
        y1[tid] = fmaxf(a, 0.f);
    }
    __syncthreads();
    if (tid < 32) {
        float a = b1[tid];
        for (int k = 0; k < 32; k++) a += y1[k] * W1[k * 32 + tid];
        y2[tid] = fmaxf(a, 0.f);
    }
    __syncthreads();
    if (tid < 32) {
        float a = b2[tid];
        for (int k = 0; k < 32; k++) a += y2[k] * W2[k * 32 + tid];
        y3[tid] = fmaxf(a, 0.f);
    }
    __syncthreads();
    if (tid < 2) {
        float a = bc[tid];
        for (int k = 0; k < 32; k++) a += y3[k] * Wc[k * 2 + tid];
        out[tid] = a;
    }
}

// ---------------- launch ----------------
extern "C" void kernel_launch(void* const* d_in, const int* in_sizes, int n_in,
                              void* d_out, int out_size) {
    (void)in_sizes; (void)n_in; (void)out_size;
    const int*   h_tok     = (const int*)d_in[0];
    const int*   e_tok     = (const int*)d_in[1];
    const int*   src       = (const int*)d_in[2];
    const int*   dst       = (const int*)d_in[3];
    const float* tok_emb   = (const float*)d_in[4];
    const float* e_tok_emb = (const float*)d_in[5];
    const float* W_ni      = (const float*)d_in[6];
    const float* W_nj      = (const float*)d_in[7];
    const float* W_fij     = (const float*)d_in[8];
    const float* b_edge    = (const float*)d_in[9];
    const float* attn      = (const float*)d_in[10];
    const float* W_node    = (const float*)d_in[11];
    const float* W_lin     = (const float*)d_in[12];
    const float* b_lin     = (const float*)d_in[13];
    const float* W1        = (const float*)d_in[14];
    const float* b1        = (const float*)d_in[15];
    const float* W2        = (const float*)d_in[16];
    const float* b2        = (const float*)d_in[17];
    const float* Wc        = (const float*)d_in[18];
    const float* bc        = (const float*)d_in[19];
    float* out = (float*)d_out;

    const int EB = (EE + 255) / 256;          // 6250
    const int NB = (NN * DD + 255) / 256;     // 6250
    const int WB = (NN + 7) / 8;              // 6250 (warp-per-node, 8 warps/block)

    k_zero_hist<<<(NN + 255) / 256, 256>>>();
    k_hist<<<EB, 256>>>(dst);
    k_scan<<<1, 1024>>>();
    k_scatter<<<EB, 256>>>(dst);
    k_gather<<<EB, 256>>>(src, dst, e_tok, e_tok_emb);
    k_hinit<<<NB, 256>>>(h_tok, tok_emb);

    for (int l = 0; l < NLAYERS; l++) {
        k_proj<<<WB, 256>>>(W_ni + l * 1024, W_nj + l * 1024, W_node + l * 1024, b_edge + l * 32);
        k_edge<<<EB, 256>>>(W_fij + l * 1024, attn + l * 32, l & 1);
        k_agg<<<WB, 256>>>();
    }

    k_rowmax<<<WB, 256>>>();
    k_head<<<1, 256>>>(W_lin, b_lin, W1, b1, W2, b2, Wc, bc, out);
}

// round 2
// speedup vs baseline: 1.3559x; 1.3559x over previous
#include <cuda_runtime.h>
#include <cuda_bf16.h>

#define NN 50000
#define EE 1600000
#define DD 32
#define NLAYERS 8
#define TOPK 8

// ---------------- device scratch (static, no allocations) ----------------
__device__ float g_h [NN*DD];
__device__ float g_hi[NN*DD];
__device__ float g_hj[NN*DD];
__device__ float g_hn[NN*DD];
__device__ float g_e [EE*DD];
__device__ float g_f [EE*DD];
__device__ float g_logits[EE];
__device__ int   g_srcS[EE];
__device__ int   g_dstS[EE];
__device__ int   g_perm[EE];
__device__ int   g_hist[NN];
__device__ int   g_row [NN+1];
__device__ int   g_cursor[NN];
__device__ float g_rowmax[NN];

__device__ __forceinline__ unsigned f2tf32(float x) {
    unsigned r;
    asm("cvt.rna.tf32.f32 %0, %1;" : "=r"(r) : "f"(x));
    return r;
}

// ---------------- CSR build (counting sort by dst) ----------------
__global__ void k_zero_hist() {
    int i = blockIdx.x * blockDim.x + threadIdx.x;
    if (i < NN) g_hist[i] = 0;
}

__global__ void k_hist(const int* __restrict__ dst) {
    int i = blockIdx.x * blockDim.x + threadIdx.x;
    if (i < EE) atomicAdd(&g_hist[dst[i]], 1);
}

__global__ void k_scan() {
    __shared__ int sm[1024];
    int t = threadIdx.x;
    const int CH = (NN + 1023) / 1024;
    int b0 = t * CH;
    int b1 = min(b0 + CH, NN);
    int sum = 0;
    for (int i = b0; i < b1; i++) sum += g_hist[i];
    sm[t] = sum;
    __syncthreads();
    for (int off = 1; off < 1024; off <<= 1) {
        int v = (t >= off) ? sm[t - off] : 0;
        __syncthreads();
        sm[t] += v;
        __syncthreads();
    }
    int pre = sm[t] - sum;
    for (int i = b0; i < b1; i++) {
        g_row[i] = pre;
        g_cursor[i] = pre;
        pre += g_hist[i];
    }
    if (t == 1023) g_row[NN] = sm[1023];
}

__global__ void k_scatter(const int* __restrict__ dst) {
    int i = blockIdx.x * blockDim.x + threadIdx.x;
    if (i < EE) {
        int d = dst[i];
        int p = atomicAdd(&g_cursor[d], 1);
        g_perm[p] = i;
    }
}

__global__ void k_gather(const int* __restrict__ src, const int* __restrict__ dst,
                         const int* __restrict__ e_tok, const float* __restrict__ e_emb) {
    int i = blockIdx.x * blockDim.x + threadIdx.x;
    if (i >= EE) return;
    int o = g_perm[i];
    g_srcS[i] = src[o];
    g_dstS[i] = dst[o];
    int tok = e_tok[o];
    const float4* eb = (const float4*)e_emb;
    float4* eo = (float4*)g_e;
#pragma unroll
    for (int q = 0; q < 8; q++) eo[(size_t)i * 8 + q] = eb[tok * 8 + q];
}

__global__ void k_hinit(const int* __restrict__ h_tok, const float* __restrict__ tok_emb) {
    int idx = blockIdx.x * blockDim.x + threadIdx.x;
    if (idx >= NN * DD) return;
    int n = idx >> 5, d = idx & 31;
    float v = tok_emb[h_tok[n] * DD + d];
    g_h[idx] = fmaxf(v, 0.f);
}

// ---------------- per-layer kernels ----------------
// node projections: hi = h@Wni + b, hj = h@Wnj, hn = h@Wnode. Warp per node.
__global__ void k_proj(const float* __restrict__ Wni, const float* __restrict__ Wnj,
                       const float* __restrict__ Wn, const float* __restrict__ b) {
    __shared__ float wi[32][32], wj[32][32], wn[32][32];
    __shared__ float bs[32];
    int tid = threadIdx.x;
    for (int i = tid; i < 1024; i += 256) {
        wi[i >> 5][i & 31] = Wni[i];
        wj[i >> 5][i & 31] = Wnj[i];
        wn[i >> 5][i & 31] = Wn[i];
    }
    if (tid < 32) bs[tid] = b[tid];
    __syncthreads();
    int node = blockIdx.x * 8 + (tid >> 5);
    int lane = tid & 31;
    if (node >= NN) return;
    float hv = g_h[node * DD + lane];
    float ai = bs[lane], aj = 0.f, an = 0.f;
#pragma unroll
    for (int k = 0; k < 32; k++) {
        float hk = __shfl_sync(0xffffffffu, hv, k);
        ai += hk * wi[k][lane];
        aj += hk * wj[k][lane];
        an += hk * wn[k][lane];
    }
    g_hi[node * DD + lane] = ai;
    g_hj[node * DD + lane] = aj;
    g_hn[node * DD + lane] = an;
}

// Edge kernel, tensor-core version.
// f = lrelu(hi[src] + hj[dst] + e@Wfij); logit = dot(f, attn)
// warp-tile: 16 edges x 32 outputs via mma.sync.m16n8k8 tf32 (3xTF32 split).
__global__ void __launch_bounds__(256, 4)
k_edge_mma(const float* __restrict__ Wf, const float* __restrict__ attn, int swap) {
    // bfrag[ks][nf][lane] = {b0_big, b0_small, b1_big, b1_small} (tf32 bit patterns)
    __shared__ float4 bfrag[4][4][32];
    __shared__ float As[32];
    int tid = threadIdx.x;
    // stage weight fragments (512 entries, 2 per thread)
#pragma unroll
    for (int e2 = 0; e2 < 2; e2++) {
        int eid = tid + e2 * 256;
        int ks = eid >> 7, nf = (eid >> 5) & 3, ln = eid & 31;
        int k0 = ks * 8 + (ln & 3);
        int n  = nf * 8 + (ln >> 2);
        float b0 = Wf[k0 * 32 + n];
        float b1 = Wf[(k0 + 4) * 32 + n];
        unsigned b0b = f2tf32(b0);
        unsigned b0s = f2tf32(b0 - __uint_as_float(b0b));
        unsigned b1b = f2tf32(b1);
        unsigned b1s = f2tf32(b1 - __uint_as_float(b1b));
        bfrag[ks][nf][ln] = make_float4(__uint_as_float(b0b), __uint_as_float(b0s),
                                        __uint_as_float(b1b), __uint_as_float(b1s));
    }
    if (tid < 32) As[tid] = attn[tid];
    __syncthreads();

    int warp = tid >> 5;
    int lane = tid & 31;
    int base = (blockIdx.x * 8 + warp) * 16;   // 16 edges per warp
    if (base >= EE) return;

    const float* ein = swap ? g_f : g_e;
    float*       fout = swap ? g_e : g_f;

    int r0 = lane >> 2;          // row within tile
    int r1 = r0 + 8;
    int c0 = lane & 3;           // k-col within kstep

    float acc[4][4];
#pragma unroll
    for (int nf = 0; nf < 4; nf++)
#pragma unroll
        for (int q = 0; q < 4; q++) acc[nf][q] = 0.f;

    const float* ebase = ein + (size_t)base * 32;
#pragma unroll
    for (int ks = 0; ks < 4; ks++) {
        float a0f = ebase[r0 * 32 + ks * 8 + c0];
        float a1f = ebase[r1 * 32 + ks * 8 + c0];
        float a2f = ebase[r0 * 32 + ks * 8 + c0 + 4];
        float a3f = ebase[r1 * 32 + ks * 8 + c0 + 4];
        unsigned ab0 = f2tf32(a0f), ab1 = f2tf32(a1f), ab2 = f2tf32(a2f), ab3 = f2tf32(a3f);
        unsigned as0 = f2tf32(a0f - __uint_as_float(ab0));
        unsigned as1 = f2tf32(a1f - __uint_as_float(ab1));
        unsigned as2 = f2tf32(a2f - __uint_as_float(ab2));
        unsigned as3 = f2tf32(a3f - __uint_as_float(ab3));
#pragma unroll
        for (int nf = 0; nf < 4; nf++) {
            float4 bv = bfrag[ks][nf][lane];
            unsigned b0b = __float_as_uint(bv.x), b0s = __float_as_uint(bv.y);
            unsigned b1b = __float_as_uint(bv.z), b1s = __float_as_uint(bv.w);
            asm volatile(
                "mma.sync.aligned.m16n8k8.row.col.f32.tf32.tf32.f32 "
                "{%0,%1,%2,%3}, {%4,%5,%6,%7}, {%8,%9}, {%0,%1,%2,%3};"
                : "+f"(acc[nf][0]), "+f"(acc[nf][1]), "+f"(acc[nf][2]), "+f"(acc[nf][3])
                : "r"(ab0), "r"(ab1), "r"(ab2), "r"(ab3), "r"(b0b), "r"(b1b));
            asm volatile(
                "mma.sync.aligned.m16n8k8.row.col.f32.tf32.tf32.f32 "
                "{%0,%1,%2,%3}, {%4,%5,%6,%7}, {%8,%9}, {%0,%1,%2,%3};"
                : "+f"(acc[nf][0]), "+f"(acc[nf][1]), "+f"(acc[nf][2]), "+f"(acc[nf][3])
                : "r"(ab0), "r"(ab1), "r"(ab2), "r"(ab3), "r"(b0s), "r"(b1s));
            asm volatile(
                "mma.sync.aligned.m16n8k8.row.col.f32.tf32.tf32.f32 "
                "{%0,%1,%2,%3}, {%4,%5,%6,%7}, {%8,%9}, {%0,%1,%2,%3};"
                : "+f"(acc[nf][0]), "+f"(acc[nf][1]), "+f"(acc[nf][2]), "+f"(acc[nf][3])
                : "r"(as0), "r"(as1), "r"(as2), "r"(as3), "r"(b0b), "r"(b1b));
        }
    }

    // epilogue: add hi[src]+hj[dst], leakyrelu, logit, store
    int s0 = g_srcS[base + r0], s1 = g_srcS[base + r1];
    int d0 = g_dstS[base + r0], d1 = g_dstS[base + r1];
    const float2* hi2 = (const float2*)g_hi;
    const float2* hj2 = (const float2*)g_hj;
    float2* f2o = (float2*)fout;

    float p0 = 0.f, p1 = 0.f;
#pragma unroll
    for (int nf = 0; nf < 4; nf++) {
        int n0 = nf * 8 + (lane & 3) * 2;     // even col
        float2 hia = hi2[s0 * 16 + n0 / 2];
        float2 hja = hj2[d0 * 16 + n0 / 2];
        float2 hib = hi2[s1 * 16 + n0 / 2];
        float2 hjb = hj2[d1 * 16 + n0 / 2];
        float v0 = acc[nf][0] + hia.x + hja.x;
        float v1 = acc[nf][1] + hia.y + hja.y;
        float v2 = acc[nf][2] + hib.x + hjb.x;
        float v3 = acc[nf][3] + hib.y + hjb.y;
        v0 = (v0 > 0.f) ? v0 : 0.01f * v0;
        v1 = (v1 > 0.f) ? v1 : 0.01f * v1;
        v2 = (v2 > 0.f) ? v2 : 0.01f * v2;
        v3 = (v3 > 0.f) ? v3 : 0.01f * v3;
        float a0 = As[n0], a1 = As[n0 + 1];
        p0 += v0 * a0 + v1 * a1;
        p1 += v2 * a0 + v3 * a1;
        f2o[(size_t)(base + r0) * 16 + n0 / 2] = make_float2(v0, v1);
        f2o[(size_t)(base + r1) * 16 + n0 / 2] = make_float2(v2, v3);
    }
    // reduce logit partials across the 4-lane quad (lane bits 0,1)
    p0 += __shfl_xor_sync(0xffffffffu, p0, 1);
    p0 += __shfl_xor_sync(0xffffffffu, p0, 2);
    p1 += __shfl_xor_sync(0xffffffffu, p1, 1);
    p1 += __shfl_xor_sync(0xffffffffu, p1, 2);
    if ((lane & 3) == 0) {
        g_logits[base + r0] = p0;
        g_logits[base + r1] = p1;
    }
}

// aggregation: edge softmax over incoming edges + weighted sum of hn[src], relu.
__global__ void k_agg() {
    int node = (blockIdx.x * blockDim.x + threadIdx.x) >> 5;
    int lane = threadIdx.x & 31;
    if (node >= NN) return;
    int beg = g_row[node], end = g_row[node + 1];
    float m = -1e30f;
    for (int i = beg + lane; i < end; i += 32) m = fmaxf(m, g_logits[i]);
#pragma unroll
    for (int o = 16; o; o >>= 1) m = fmaxf(m, __shfl_xor_sync(0xffffffffu, m, o));
    float s = 0.f, acc = 0.f;
    for (int i = beg; i < end; i++) {
        float w = __expf(g_logits[i] - m);
        s += w;
        acc += w * g_hn[g_srcS[i] * DD + lane];
    }
    float hv = (end > beg) ? (acc / s) : 0.f;
    g_h[node * DD + lane] = fmaxf(hv, 0.f);
}

// ---------------- SortPooling + MLP head ----------------
__global__ void k_rowmax() {
    int node = (blockIdx.x * blockDim.x + threadIdx.x) >> 5;
    int lane = threadIdx.x & 31;
    if (node >= NN) return;
    float v = g_h[node * DD + lane];
#pragma unroll
    for (int o = 16; o; o >>= 1) v = fmaxf(v, __shfl_xor_sync(0xffffffffu, v, o));
    if (lane == 0) g_rowmax[node] = v;
}

__global__ void k_head(const float* __restrict__ Wlin, const float* __restrict__ blin,
                       const float* __restrict__ W1, const float* __restrict__ b1,
                       const float* __restrict__ W2, const float* __restrict__ b2,
                       const float* __restrict__ Wc, const float* __restrict__ bc,
                       float* __restrict__ out) {
    __shared__ float sv[256];
    __shared__ int si[256];
    __shared__ int picked[TOPK];
    __shared__ float xs[TOPK * DD];
    __shared__ float y1[32], y2[32], y3[32];
    int tid = threadIdx.x;

    for (int t = 0; t < TOPK; t++) {
        float best = -1e30f;
        int bidx = 0x7fffffff;
        for (int i = tid; i < NN; i += 256) {
            bool skip = false;
            for (int p = 0; p < t; p++)
                if (picked[p] == i) skip = true;
            if (skip) continue;
            float v = g_rowmax[i];
            if (v > best || (v == best && i < bidx)) { best = v; bidx = i; }
        }
        sv[tid] = best;
        si[tid] = bidx;
        __syncthreads();
        for (int off = 128; off; off >>= 1) {
            if (tid < off) {
                float v2 = sv[tid + off];
                int i2 = si[tid + off];
                if (v2 > sv[tid] || (v2 == sv[tid] && i2 < si[tid])) {
                    sv[tid] = v2;
                    si[tid] = i2;
                }
            }
            __syncthreads();
        }
        if (tid == 0) picked[t] = si[0];
        __syncthreads();
    }

    if (tid < TOPK) {
        float r[32];
        int n = picked[tid];
        for (int d = 0; d < 32; d++) r[d] = g_h[n * DD + d];
        for (int a = 1; a < 32; a++) {
            float key = r[a];
            int b = a - 1;
            while (b >= 0 && r[b] > key) { r[b + 1] = r[b]; b--; }
            r[b + 1] = key;
        }
        for (int d = 0; d < 32; d++) xs[tid * 32 + d] = r[d];
    }
    __syncthreads();

    if (tid < 32) {
        float a = blin[tid];
        for (int i = 0; i < 256; i++) a += xs[i] * Wlin[i * 32 + tid];
        y1[tid] = fmaxf(a, 0.f);
    }
    __syncthreads();
    if (tid < 32) {
        float a = b1[tid];
        for (int k = 0; k < 32; k++) a += y1[k] * W1[k * 32 + tid];
        y2[tid] = fmaxf(a, 0.f);
    }
    __syncthreads();
    if (tid < 32) {
        float a = b2[tid];
        for (int k = 0; k < 32; k++) a += y2[k] * W2[k * 32 + tid];
        y3[tid] = fmaxf(a, 0.f);
    }
    __syncthreads();
    if (tid < 2) {
        float a = bc[tid];
        for (int k = 0; k < 32; k++) a += y3[k] * Wc[k * 2 + tid];
        out[tid] = a;
    }
}

// ---------------- launch ----------------
extern "C" void kernel_launch(void* const* d_in, const int* in_sizes, int n_in,
                              void* d_out, int out_size) {
    (void)in_sizes; (void)n_in; (void)out_size;
    const int*   h_tok     = (const int*)d_in[0];
    const int*   e_tok     = (const int*)d_in[1];
    const int*   src       = (const int*)d_in[2];
    const int*   dst       = (const int*)d_in[3];
    const float* tok_emb   = (const float*)d_in[4];
    const float* e_tok_emb = (const float*)d_in[5];
    const float* W_ni      = (const float*)d_in[6];
    const float* W_nj      = (const float*)d_in[7];
    const float* W_fij     = (const float*)d_in[8];
    const float* b_edge    = (const float*)d_in[9];
    const float* attn      = (const float*)d_in[10];
    const float* W_node    = (const float*)d_in[11];
    const float* W_lin     = (const float*)d_in[12];
    const float* b_lin     = (const float*)d_in[13];
    const float* W1        = (const float*)d_in[14];
    const float* b1        = (const float*)d_in[15];
    const float* W2        = (const float*)d_in[16];
    const float* b2        = (const float*)d_in[17];
    const float* Wc        = (const float*)d_in[18];
    const float* bc        = (const float*)d_in[19];
    float* out = (float*)d_out;

    const int EB = (EE + 255) / 256;          // 6250
    const int NB = (NN * DD + 255) / 256;     // 6250
    const int WB = (NN + 7) / 8;              // 6250
    const int MB = (EE + 127) / 128;          // 12500 (128 edges per block)

    k_zero_hist<<<(NN + 255) / 256, 256>>>();
    k_hist<<<EB, 256>>>(dst);
    k_scan<<<1, 1024>>>();
    k_scatter<<<EB, 256>>>(dst);
    k_gather<<<EB, 256>>>(src, dst, e_tok, e_tok_emb);
    k_hinit<<<NB, 256>>>(h_tok, tok_emb);

    for (int l = 0; l < NLAYERS; l++) {
        k_proj<<<WB, 256>>>(W_ni + l * 1024, W_nj + l * 1024, W_node + l * 1024, b_edge + l * 32);
        k_edge_mma<<<MB, 256>>>(W_fij + l * 1024, attn + l * 32, l & 1);
        k_agg<<<WB, 256>>>();
    }

    k_rowmax<<<WB, 256>>>();
    k_head<<<1, 256>>>(W_lin, b_lin, W1, b1, W2, b2, Wc, bc, out);
}

// round 3
// speedup vs baseline: 1.5065x; 1.1110x over previous
#include <cuda_runtime.h>
#include <cuda_bf16.h>

#define NN 50000
#define EE 1600000
#define DD 32
#define NLAYERS 8
#define TOPK 8

// ---------------- device scratch (static, no allocations) ----------------
__device__ float g_h [NN*DD];
__device__ float g_hi[NN*DD];
__device__ float g_hj[NN*DD];
__device__ float g_hn[NN*DD];
// e/f stored in MMA A-fragment tiled layout:
// tile = edge/16 ; float4 F4[tile][4(ks)][32(lane)]
// F4[ks][lane] = { e[r0][ks*8+c0], e[r1][ks*8+c0], e[r0][ks*8+c0+4], e[r1][ks*8+c0+4] }
//   with r0 = lane>>2, r1 = r0+8, c0 = lane&3   (rows within the 16-edge tile)
__device__ float g_e [EE*DD];
__device__ float g_f [EE*DD];
__device__ float g_logits[EE];
__device__ int   g_srcS[EE];
__device__ int   g_dstS[EE];
__device__ int   g_perm[EE];
__device__ int   g_hist[NN];
__device__ int   g_row [NN+1];
__device__ int   g_cursor[NN];
__device__ float g_rowmax[NN];

__device__ __forceinline__ unsigned f2tf32(float x) {
    unsigned r;
    asm("cvt.rna.tf32.f32 %0, %1;" : "=r"(r) : "f"(x));
    return r;
}

// ---------------- CSR build (counting sort by dst) ----------------
__global__ void k_zero_hist() {
    int i = blockIdx.x * blockDim.x + threadIdx.x;
    if (i < NN) g_hist[i] = 0;
}

__global__ void k_hist(const int* __restrict__ dst) {
    int i = blockIdx.x * blockDim.x + threadIdx.x;
    if (i < EE) atomicAdd(&g_hist[dst[i]], 1);
}

__global__ void k_scan() {
    __shared__ int sm[1024];
    int t = threadIdx.x;
    const int CH = (NN + 1023) / 1024;
    int b0 = t * CH;
    int b1 = min(b0 + CH, NN);
    int sum = 0;
    for (int i = b0; i < b1; i++) sum += g_hist[i];
    sm[t] = sum;
    __syncthreads();
    for (int off = 1; off < 1024; off <<= 1) {
        int v = (t >= off) ? sm[t - off] : 0;
        __syncthreads();
        sm[t] += v;
        __syncthreads();
    }
    int pre = sm[t] - sum;
    for (int i = b0; i < b1; i++) {
        g_row[i] = pre;
        g_cursor[i] = pre;
        pre += g_hist[i];
    }
    if (t == 1023) g_row[NN] = sm[1023];
}

__global__ void k_scatter(const int* __restrict__ dst) {
    int i = blockIdx.x * blockDim.x + threadIdx.x;
    if (i < EE) {
        int d = dst[i];
        int p = atomicAdd(&g_cursor[d], 1);
        g_perm[p] = i;
    }
}

// write initial e in the tiled fragment layout
__global__ void k_gather(const int* __restrict__ src, const int* __restrict__ dst,
                         const int* __restrict__ e_tok, const float* __restrict__ e_emb) {
    int i = blockIdx.x * blockDim.x + threadIdx.x;
    if (i >= EE) return;
    int o = g_perm[i];
    g_srcS[i] = src[o];
    g_dstS[i] = dst[o];
    int tok = e_tok[o];
    const float* eb = e_emb + tok * DD;
    int tile = i >> 4;
    int r = i & 15;
    int half = r >> 3;       // comp offset 0/1
    int r0 = r & 7;
    float* base = g_e + (size_t)tile * 512;
#pragma unroll
    for (int c = 0; c < 32; c++) {
        int ks = c >> 3, cc = c & 7;
        int lane = r0 * 4 + (cc & 3);
        int comp = half + ((cc >= 4) ? 2 : 0);
        base[ks * 128 + lane * 4 + comp] = eb[c];
    }
}

__global__ void k_hinit(const int* __restrict__ h_tok, const float* __restrict__ tok_emb) {
    int idx = blockIdx.x * blockDim.x + threadIdx.x;
    if (idx >= NN * DD) return;
    int n = idx >> 5, d = idx & 31;
    float v = tok_emb[h_tok[n] * DD + d];
    g_h[idx] = fmaxf(v, 0.f);
}

// ---------------- per-layer kernels ----------------
__global__ void k_proj(const float* __restrict__ Wni, const float* __restrict__ Wnj,
                       const float* __restrict__ Wn, const float* __restrict__ b) {
    __shared__ float wi[32][32], wj[32][32], wn[32][32];
    __shared__ float bs[32];
    int tid = threadIdx.x;
    for (int i = tid; i < 1024; i += 256) {
        wi[i >> 5][i & 31] = Wni[i];
        wj[i >> 5][i & 31] = Wnj[i];
        wn[i >> 5][i & 31] = Wn[i];
    }
    if (tid < 32) bs[tid] = b[tid];
    __syncthreads();
    int node = blockIdx.x * 8 + (tid >> 5);
    int lane = tid & 31;
    if (node >= NN) return;
    float hv = g_h[node * DD + lane];
    float ai = bs[lane], aj = 0.f, an = 0.f;
#pragma unroll
    for (int k = 0; k < 32; k++) {
        float hk = __shfl_sync(0xffffffffu, hv, k);
        ai += hk * wi[k][lane];
        aj += hk * wj[k][lane];
        an += hk * wn[k][lane];
    }
    g_hi[node * DD + lane] = ai;
    g_hj[node * DD + lane] = aj;
    g_hn[node * DD + lane] = an;
}

// Edge kernel: f = lrelu(hi[src] + hj[dst] + e@Wfij); logit = dot(f, attn)
// 16 edges per warp via mma.sync.m16n8k8 tf32 (3xTF32 split).
// e/f in tiled fragment layout -> all global traffic is 128b coalesced.
__global__ void __launch_bounds__(256, 4)
k_edge_mma(const float* __restrict__ Wf, const float* __restrict__ attn, int swap) {
    __shared__ float4 bfrag[4][4][32];
    __shared__ float As[32];
    int tid = threadIdx.x;
#pragma unroll
    for (int e2 = 0; e2 < 2; e2++) {
        int eid = tid + e2 * 256;
        int ks = eid >> 7, nf = (eid >> 5) & 3, ln = eid & 31;
        int k0 = ks * 8 + (ln & 3);
        int n  = nf * 8 + (ln >> 2);
        float b0 = Wf[k0 * 32 + n];
        float b1 = Wf[(k0 + 4) * 32 + n];
        unsigned b0b = f2tf32(b0);
        unsigned b0s = f2tf32(b0 - __uint_as_float(b0b));
        unsigned b1b = f2tf32(b1);
        unsigned b1s = f2tf32(b1 - __uint_as_float(b1b));
        bfrag[ks][nf][ln] = make_float4(__uint_as_float(b0b), __uint_as_float(b0s),
                                        __uint_as_float(b1b), __uint_as_float(b1s));
    }
    if (tid < 32) As[tid] = attn[tid];
    __syncthreads();

    int warp = tid >> 5;
    int lane = tid & 31;
    int base = (blockIdx.x * 8 + warp) * 16;
    if (base >= EE) return;
    int tile = base >> 4;

    const float4* ein4 = (const float4*)(swap ? g_f : g_e);
    float4*       fout4 = (float4*)(swap ? g_e : g_f);

    int r0 = lane >> 2;
    int r1 = r0 + 8;

    float acc[4][4];
#pragma unroll
    for (int nf = 0; nf < 4; nf++)
#pragma unroll
        for (int q = 0; q < 4; q++) acc[nf][q] = 0.f;

#pragma unroll
    for (int ks = 0; ks < 4; ks++) {
        float4 va = ein4[(size_t)tile * 128 + ks * 32 + lane];
        unsigned ab0 = f2tf32(va.x), ab1 = f2tf32(va.y), ab2 = f2tf32(va.z), ab3 = f2tf32(va.w);
        unsigned as0 = f2tf32(va.x - __uint_as_float(ab0));
        unsigned as1 = f2tf32(va.y - __uint_as_float(ab1));
        unsigned as2 = f2tf32(va.z - __uint_as_float(ab2));
        unsigned as3 = f2tf32(va.w - __uint_as_float(ab3));
#pragma unroll
        for (int nf = 0; nf < 4; nf++) {
            float4 bv = bfrag[ks][nf][lane];
            unsigned b0b = __float_as_uint(bv.x), b0s = __float_as_uint(bv.y);
            unsigned b1b = __float_as_uint(bv.z), b1s = __float_as_uint(bv.w);
            asm volatile(
                "mma.sync.aligned.m16n8k8.row.col.f32.tf32.tf32.f32 "
                "{%0,%1,%2,%3}, {%4,%5,%6,%7}, {%8,%9}, {%0,%1,%2,%3};"
                : "+f"(acc[nf][0]), "+f"(acc[nf][1]), "+f"(acc[nf][2]), "+f"(acc[nf][3])
                : "r"(ab0), "r"(ab1), "r"(ab2), "r"(ab3), "r"(b0b), "r"(b1b));
            asm volatile(
                "mma.sync.aligned.m16n8k8.row.col.f32.tf32.tf32.f32 "
                "{%0,%1,%2,%3}, {%4,%5,%6,%7}, {%8,%9}, {%0,%1,%2,%3};"
                : "+f"(acc[nf][0]), "+f"(acc[nf][1]), "+f"(acc[nf][2]), "+f"(acc[nf][3])
                : "r"(ab0), "r"(ab1), "r"(ab2), "r"(ab3), "r"(b0s), "r"(b1s));
            asm volatile(
                "mma.sync.aligned.m16n8k8.row.col.f32.tf32.tf32.f32 "
                "{%0,%1,%2,%3}, {%4,%5,%6,%7}, {%8,%9}, {%0,%1,%2,%3};"
                : "+f"(acc[nf][0]), "+f"(acc[nf][1]), "+f"(acc[nf][2]), "+f"(acc[nf][3])
                : "r"(as0), "r"(as1), "r"(as2), "r"(as3), "r"(b0b), "r"(b1b));
        }
    }

    // epilogue in c-fragment layout: add hi[src]+hj[dst], leakyrelu, logit
    int s0 = g_srcS[base + r0], s1 = g_srcS[base + r1];
    int d0 = g_dstS[base + r0], d1 = g_dstS[base + r1];
    const float2* hi2 = (const float2*)g_hi;
    const float2* hj2 = (const float2*)g_hj;

    int t = lane & 3;
    int srcA = (lane & 28) | (t >> 1);
    int srcB = srcA | 2;

    float p0 = 0.f, p1 = 0.f;
#pragma unroll
    for (int nf = 0; nf < 4; nf++) {
        int n0 = nf * 8 + t * 2;
        float2 hia = hi2[s0 * 16 + n0 / 2];
        float2 hja = hj2[d0 * 16 + n0 / 2];
        float2 hib = hi2[s1 * 16 + n0 / 2];
        float2 hjb = hj2[d1 * 16 + n0 / 2];
        float v0 = acc[nf][0] + hia.x + hja.x;
        float v1 = acc[nf][1] + hia.y + hja.y;
        float v2 = acc[nf][2] + hib.x + hjb.x;
        float v3 = acc[nf][3] + hib.y + hjb.y;
        v0 = (v0 > 0.f) ? v0 : 0.01f * v0;
        v1 = (v1 > 0.f) ? v1 : 0.01f * v1;
        v2 = (v2 > 0.f) ? v2 : 0.01f * v2;
        v3 = (v3 > 0.f) ? v3 : 0.01f * v3;
        float a0 = As[n0], a1 = As[n0 + 1];
        p0 += v0 * a0 + v1 * a1;
        p1 += v2 * a0 + v3 * a1;

        // convert (v0,v1)/(v2,v3) [cols 2t,2t+1] -> a-layout [cols t, t+4]
        float y0 = __shfl_sync(0xffffffffu, v0, srcA);
        float y1 = __shfl_sync(0xffffffffu, v1, srcA);
        float z0 = __shfl_sync(0xffffffffu, v0, srcB);
        float z1 = __shfl_sync(0xffffffffu, v1, srcB);
        float u0r0 = (t & 1) ? y1 : y0;   // (r0, col t)
        float u1r0 = (t & 1) ? z1 : z0;   // (r0, col t+4)
        float y2 = __shfl_sync(0xffffffffu, v2, srcA);
        float y3 = __shfl_sync(0xffffffffu, v3, srcA);
        float z2 = __shfl_sync(0xffffffffu, v2, srcB);
        float z3 = __shfl_sync(0xffffffffu, v3, srcB);
        float u0r1 = (t & 1) ? y3 : y2;   // (r1, col t)
        float u1r1 = (t & 1) ? z3 : z2;   // (r1, col t+4)

        fout4[(size_t)tile * 128 + nf * 32 + lane] = make_float4(u0r0, u0r1, u1r0, u1r1);
    }
    p0 += __shfl_xor_sync(0xffffffffu, p0, 1);
    p0 += __shfl_xor_sync(0xffffffffu, p0, 2);
    p1 += __shfl_xor_sync(0xffffffffu, p1, 1);
    p1 += __shfl_xor_sync(0xffffffffu, p1, 2);
    if (t == 0) {
        g_logits[base + r0] = p0;
        g_logits[base + r1] = p1;
    }
}

// aggregation: edge softmax + weighted sum of hn[src], relu. Pipelined loads.
__global__ void k_agg() {
    int node = (blockIdx.x * blockDim.x + threadIdx.x) >> 5;
    int lane = threadIdx.x & 31;
    if (node >= NN) return;
    int beg = g_row[node], end = g_row[node + 1];
    float m = -1e30f;
    for (int i = beg + lane; i < end; i += 32) m = fmaxf(m, g_logits[i]);
#pragma unroll
    for (int o = 16; o; o >>= 1) m = fmaxf(m, __shfl_xor_sync(0xffffffffu, m, o));
    float s = 0.f, acc = 0.f;
    for (int chunk = beg; chunk < end; chunk += 32) {
        int i = chunk + lane;
        float w = 0.f;
        int sv = 0;
        if (i < end) {
            w = __expf(g_logits[i] - m);
            sv = g_srcS[i];
        }
        s += w;
#pragma unroll
        for (int e = 0; e < 32; e++) {
            float we = __shfl_sync(0xffffffffu, w, e);
            int se = __shfl_sync(0xffffffffu, sv, e);
            acc += we * g_hn[se * DD + lane];
        }
    }
#pragma unroll
    for (int o = 16; o; o >>= 1) s += __shfl_xor_sync(0xffffffffu, s, o);
    float hv = (end > beg) ? (acc / s) : 0.f;
    g_h[node * DD + lane] = fmaxf(hv, 0.f);
}

// ---------------- SortPooling + MLP head ----------------
__global__ void k_rowmax() {
    int node = (blockIdx.x * blockDim.x + threadIdx.x) >> 5;
    int lane = threadIdx.x & 31;
    if (node >= NN) return;
    float v = g_h[node * DD + lane];
#pragma unroll
    for (int o = 16; o; o >>= 1) v = fmaxf(v, __shfl_xor_sync(0xffffffffu, v, o));
    if (lane == 0) g_rowmax[node] = v;
}

__global__ void k_head(const float* __restrict__ Wlin, const float* __restrict__ blin,
                       const float* __restrict__ W1, const float* __restrict__ b1,
                       const float* __restrict__ W2, const float* __restrict__ b2,
                       const float* __restrict__ Wc, const float* __restrict__ bc,
                       float* __restrict__ out) {
    __shared__ float sv[256];
    __shared__ int si[256];
    __shared__ int picked[TOPK];
    __shared__ float xs[TOPK * DD];
    __shared__ float y1[32], y2[32], y3[32];
    int tid = threadIdx.x;

    for (int t = 0; t < TOPK; t++) {
        float best = -1e30f;
        int bidx = 0x7fffffff;
        for (int i = tid; i < NN; i += 256) {
            bool skip = false;
            for (int p = 0; p < t; p++)
                if (picked[p] == i) skip = true;
            if (skip) continue;
            float v = g_rowmax[i];
            if (v > best || (v == best && i < bidx)) { best = v; bidx = i; }
        }
        sv[tid] = best;
        si[tid] = bidx;
        __syncthreads();
        for (int off = 128; off; off >>= 1) {
            if (tid < off) {
                float v2 = sv[tid + off];
                int i2 = si[tid + off];
                if (v2 > sv[tid] || (v2 == sv[tid] && i2 < si[tid])) {
                    sv[tid] = v2;
                    si[tid] = i2;
                }
            }
            __syncthreads();
        }
        if (tid == 0) picked[t] = si[0];
        __syncthreads();
    }

    if (tid < TOPK) {
        float r[32];
        int n = picked[tid];
        for (int d = 0; d < 32; d++) r[d] = g_h[n * DD + d];
        for (int a = 1; a < 32; a++) {
            float key = r[a];
            int b = a - 1;
            while (b >= 0 && r[b] > key) { r[b + 1] = r[b]; b--; }
            r[b + 1] = key;
        }
        for (int d = 0; d < 32; d++) xs[tid * 32 + d] = r[d];
    }
    __syncthreads();

    if (tid < 32) {
        float a = blin[tid];
        for (int i = 0; i < 256; i++) a += xs[i] * Wlin[i * 32 + tid];
        y1[tid] = fmaxf(a, 0.f);
    }
    __syncthreads();
    if (tid < 32) {
        float a = b1[tid];
        for (int k = 0; k < 32; k++) a += y1[k] * W1[k * 32 + tid];
        y2[tid] = fmaxf(a, 0.f);
    }
    __syncthreads();
    if (tid < 32) {
        float a = b2[tid];
        for (int k = 0; k < 32; k++) a += y2[k] * W2[k * 32 + tid];
        y3[tid] = fmaxf(a, 0.f);
    }
    __syncthreads();
    if (tid < 2) {
        float a = bc[tid];
        for (int k = 0; k < 32; k++) a += y3[k] * Wc[k * 2 + tid];
        out[tid] = a;
    }
}

// ---------------- launch ----------------
extern "C" void kernel_launch(void* const* d_in, const int* in_sizes, int n_in,
                              void* d_out, int out_size) {
    (void)in_sizes; (void)n_in; (void)out_size;
    const int*   h_tok     = (const int*)d_in[0];
    const int*   e_tok     = (const int*)d_in[1];
    const int*   src       = (const int*)d_in[2];
    const int*   dst       = (const int*)d_in[3];
    const float* tok_emb   = (const float*)d_in[4];
    const float* e_tok_emb = (const float*)d_in[5];
    const float* W_ni      = (const float*)d_in[6];
    const float* W_nj      = (const float*)d_in[7];
    const float* W_fij     = (const float*)d_in[8];
    const float* b_edge    = (const float*)d_in[9];
    const float* attn      = (const float*)d_in[10];
    const float* W_node    = (const float*)d_in[11];
    const float* W_lin     = (const float*)d_in[12];
    const float* b_lin     = (const float*)d_in[13];
    const float* W1        = (const float*)d_in[14];
    const float* b1        = (const float*)d_in[15];
    const float* W2        = (const float*)d_in[16];
    const float* b2        = (const float*)d_in[17];
    const float* Wc        = (const float*)d_in[18];
    const float* bc        = (const float*)d_in[19];
    float* out = (float*)d_out;

    const int EB = (EE + 255) / 256;          // 6250
    const int NB = (NN * DD + 255) / 256;     // 6250
    const int WB = (NN + 7) / 8;              // 6250
    const int MB = (EE + 127) / 128;          // 12500

    k_zero_hist<<<(NN + 255) / 256, 256>>>();
    k_hist<<<EB, 256>>>(dst);
    k_scan<<<1, 1024>>>();
    k_scatter<<<EB, 256>>>(dst);
    k_gather<<<EB, 256>>>(src, dst, e_tok, e_tok_emb);
    k_hinit<<<NB, 256>>>(h_tok, tok_emb);

    for (int l = 0; l < NLAYERS; l++) {
        k_proj<<<WB, 256>>>(W_ni + l * 1024, W_nj + l * 1024, W_node + l * 1024, b_edge + l * 32);
        k_edge_mma<<<MB, 256>>>(W_fij + l * 1024, attn + l * 32, l & 1);
        k_agg<<<WB, 256>>>();
    }

    k_rowmax<<<WB, 256>>>();
    k_head<<<1, 256>>>(W_lin, b_lin, W1, b1, W2, b2, Wc, bc, out);
}

// round 4
// speedup vs baseline: 1.5165x; 1.0066x over previous
#include <cuda_runtime.h>
#include <cuda_bf16.h>

#define NN 50000
#define EE 1600000
#define DD 32
#define NLAYERS 8
#define TOPK 8
#define VOCAB 100

// ---------------- device scratch (static, no allocations) ----------------
__device__ float g_h [NN*DD];
__device__ float g_hi[NN*DD];
__device__ float g_hj[NN*DD];
__device__ float g_hn[NN*DD];
// e/f in MMA A-fragment tiled layout:
// tile = edge/16 ; float4 F4[tile][4(ks)][32(lane)]
// F4[ks][lane] = { e[r0][ks*8+c0], e[r1][ks*8+c0], e[r0][ks*8+c0+4], e[r1][ks*8+c0+4] }
//   r0 = lane>>2, r1 = r0+8, c0 = lane&3
__device__ float g_e [EE*DD];
__device__ float g_f [EE*DD];
__device__ float g_logits[EE];
__device__ int   g_srcS[EE];
__device__ int   g_dstS[EE];
__device__ int   g_etokS[EE];
__device__ int   g_perm[EE];
__device__ int   g_hist[NN];       // static zero-init; re-zeroed by k_scan each call
__device__ int   g_row [NN+1];
__device__ int   g_cursor[NN];
__device__ float g_rowmax[NN];

__device__ __forceinline__ unsigned f2tf32(float x) {
    unsigned r;
    asm("cvt.rna.tf32.f32 %0, %1;" : "=r"(r) : "f"(x));
    return r;
}

// ---------------- CSR build (counting sort by dst) ----------------
__global__ void k_hist(const int* __restrict__ dst) {
    int i = blockIdx.x * blockDim.x + threadIdx.x;
    if (i < EE) atomicAdd(&g_hist[dst[i]], 1);
}

__global__ void k_scan() {
    __shared__ int sm[1024];
    int t = threadIdx.x;
    const int CH = (NN + 1023) / 1024;
    int b0 = t * CH;
    int b1 = min(b0 + CH, NN);
    int sum = 0;
    for (int i = b0; i < b1; i++) sum += g_hist[i];
    sm[t] = sum;
    __syncthreads();
    for (int off = 1; off < 1024; off <<= 1) {
        int v = (t >= off) ? sm[t - off] : 0;
        __syncthreads();
        sm[t] += v;
        __syncthreads();
    }
    int pre = sm[t] - sum;
    for (int i = b0; i < b1; i++) {
        g_row[i] = pre;
        g_cursor[i] = pre;
        pre += g_hist[i];
        g_hist[i] = 0;            // re-zero for the next kernel_launch call
    }
    if (t == 1023) g_row[NN] = sm[1023];
}

__global__ void k_scatter(const int* __restrict__ dst) {
    int i = blockIdx.x * blockDim.x + threadIdx.x;
    if (i < EE) {
        int d = dst[i];
        int p = atomicAdd(&g_cursor[d], 1);
        g_perm[p] = i;
    }
}

__global__ void k_gather(const int* __restrict__ src, const int* __restrict__ dst,
                         const int* __restrict__ e_tok) {
    int i = blockIdx.x * blockDim.x + threadIdx.x;
    if (i >= EE) return;
    int o = g_perm[i];
    g_srcS[i] = src[o];
    g_dstS[i] = dst[o];
    g_etokS[i] = e_tok[o];
}

// ---------------- fused node-side kernels ----------------
__device__ __forceinline__ void stage_w(const float* Wni, const float* Wnj,
                                        const float* Wn, const float* b,
                                        float (*wi)[32], float (*wj)[32],
                                        float (*wn)[32], float* bs, int tid) {
    for (int i = tid; i < 1024; i += 256) {
        wi[i >> 5][i & 31] = Wni[i];
        wj[i >> 5][i & 31] = Wnj[i];
        wn[i >> 5][i & 31] = Wn[i];
    }
    if (tid < 32) bs[tid] = b[tid];
}

// hinit + layer-0 projections, warp per node
__global__ void k_init_proj(const int* __restrict__ h_tok, const float* __restrict__ tok_emb,
                            const float* __restrict__ Wni, const float* __restrict__ Wnj,
                            const float* __restrict__ Wn, const float* __restrict__ b) {
    __shared__ float wi[32][32], wj[32][32], wn[32][32], bs[32];
    int tid = threadIdx.x;
    stage_w(Wni, Wnj, Wn, b, wi, wj, wn, bs, tid);
    __syncthreads();
    int node = blockIdx.x * 8 + (tid >> 5);
    int lane = tid & 31;
    if (node >= NN) return;
    float hv = fmaxf(tok_emb[h_tok[node] * DD + lane], 0.f);
    float ai = bs[lane], aj = 0.f, an = 0.f;
#pragma unroll
    for (int k = 0; k < 32; k++) {
        float hk = __shfl_sync(0xffffffffu, hv, k);
        ai += hk * wi[k][lane];
        aj += hk * wj[k][lane];
        an += hk * wn[k][lane];
    }
    g_hi[node * DD + lane] = ai;
    g_hj[node * DD + lane] = aj;
    g_hn[node * DD + lane] = an;
}

// aggregation (+ relu) fused with NEXT layer's projections; last layer does rowmax instead.
__global__ void k_aggproj(const float* __restrict__ Wni, const float* __restrict__ Wnj,
                          const float* __restrict__ Wn, const float* __restrict__ b,
                          int last) {
    __shared__ float wi[32][32], wj[32][32], wn[32][32], bs[32];
    int tid = threadIdx.x;
    if (!last) stage_w(Wni, Wnj, Wn, b, wi, wj, wn, bs, tid);
    __syncthreads();
    int node = blockIdx.x * 8 + (tid >> 5);
    int lane = tid & 31;
    if (node >= NN) return;
    int beg = g_row[node], end = g_row[node + 1];
    float m = -1e30f;
    for (int i = beg + lane; i < end; i += 32) m = fmaxf(m, g_logits[i]);
#pragma unroll
    for (int o = 16; o; o >>= 1) m = fmaxf(m, __shfl_xor_sync(0xffffffffu, m, o));
    float s = 0.f, acc = 0.f;
    for (int chunk = beg; chunk < end; chunk += 32) {
        int i = chunk + lane;
        float w = 0.f;
        int sv = 0;
        if (i < end) {
            w = __expf(g_logits[i] - m);
            sv = g_srcS[i];
        }
        s += w;
#pragma unroll
        for (int e = 0; e < 32; e++) {
            float we = __shfl_sync(0xffffffffu, w, e);
            int se = __shfl_sync(0xffffffffu, sv, e);
            acc += we * g_hn[se * DD + lane];
        }
    }
#pragma unroll
    for (int o = 16; o; o >>= 1) s += __shfl_xor_sync(0xffffffffu, s, o);
    float hv = (end > beg) ? fmaxf(acc / s, 0.f) : 0.f;

    if (last) {
        g_h[node * DD + lane] = hv;
        float v = hv;
#pragma unroll
        for (int o = 16; o; o >>= 1) v = fmaxf(v, __shfl_xor_sync(0xffffffffu, v, o));
        if (lane == 0) g_rowmax[node] = v;
    } else {
        float ai = bs[lane], aj = 0.f, an = 0.f;
#pragma unroll
        for (int k = 0; k < 32; k++) {
            float hk = __shfl_sync(0xffffffffu, hv, k);
            ai += hk * wi[k][lane];
            aj += hk * wj[k][lane];
            an += hk * wn[k][lane];
        }
        g_hi[node * DD + lane] = ai;
        g_hj[node * DD + lane] = aj;
        g_hn[node * DD + lane] = an;
    }
}

// ---------------- edge kernel (tensor core, 3xTF32) ----------------
// flags: bit0 = swap (read g_f/write g_e), bit1 = first (e from token table), bit2 = last (skip f store)
__global__ void __launch_bounds__(256)
k_edge_mma(const float* __restrict__ Wf, const float* __restrict__ attn,
           const float* __restrict__ e_emb, int flags) {
    __shared__ float4 bfrag[4][4][32];
    __shared__ float As[32];
    __shared__ float etab[VOCAB][33];
    const int swap = flags & 1, first = flags & 2, lastl = flags & 4;
    int tid = threadIdx.x;
#pragma unroll
    for (int e2 = 0; e2 < 2; e2++) {
        int eid = tid + e2 * 256;
        int ks = eid >> 7, nf = (eid >> 5) & 3, ln = eid & 31;
        int k0 = ks * 8 + (ln & 3);
        int n  = nf * 8 + (ln >> 2);
        float b0 = Wf[k0 * 32 + n];
        float b1 = Wf[(k0 + 4) * 32 + n];
        unsigned b0b = f2tf32(b0);
        unsigned b0s = f2tf32(b0 - __uint_as_float(b0b));
        unsigned b1b = f2tf32(b1);
        unsigned b1s = f2tf32(b1 - __uint_as_float(b1b));
        bfrag[ks][nf][ln] = make_float4(__uint_as_float(b0b), __uint_as_float(b0s),
                                        __uint_as_float(b1b), __uint_as_float(b1s));
    }
    if (tid < 32) As[tid] = attn[tid];
    if (first) {
        for (int i = tid; i < VOCAB * DD; i += 256)
            etab[i >> 5][i & 31] = e_emb[i];
    }
    __syncthreads();

    int warp = tid >> 5;
    int lane = tid & 31;
    int base = (blockIdx.x * 8 + warp) * 16;
    if (base >= EE) return;
    int tile = base >> 4;

    const float4* ein4 = (const float4*)(swap ? g_f : g_e);
    float4*       fout4 = (float4*)(swap ? g_e : g_f);

    int r0 = lane >> 2;
    int r1 = r0 + 8;
    int c0 = lane & 3;

    // prefetch epilogue indices early
    int s0 = g_srcS[base + r0], s1 = g_srcS[base + r1];
    int d0 = g_dstS[base + r0], d1 = g_dstS[base + r1];
    int t0 = 0, t1 = 0;
    if (first) { t0 = g_etokS[base + r0]; t1 = g_etokS[base + r1]; }

    float acc[4][4];
#pragma unroll
    for (int nf = 0; nf < 4; nf++)
#pragma unroll
        for (int q = 0; q < 4; q++) acc[nf][q] = 0.f;

#pragma unroll
    for (int ks = 0; ks < 4; ks++) {
        float4 va;
        if (first) {
            va.x = etab[t0][ks * 8 + c0];
            va.y = etab[t1][ks * 8 + c0];
            va.z = etab[t0][ks * 8 + c0 + 4];
            va.w = etab[t1][ks * 8 + c0 + 4];
        } else {
            va = ein4[(size_t)tile * 128 + ks * 32 + lane];
        }
        unsigned ab0 = f2tf32(va.x), ab1 = f2tf32(va.y), ab2 = f2tf32(va.z), ab3 = f2tf32(va.w);
        unsigned as0 = f2tf32(va.x - __uint_as_float(ab0));
        unsigned as1 = f2tf32(va.y - __uint_as_float(ab1));
        unsigned as2 = f2tf32(va.z - __uint_as_float(ab2));
        unsigned as3 = f2tf32(va.w - __uint_as_float(ab3));
#pragma unroll
        for (int nf = 0; nf < 4; nf++) {
            float4 bv = bfrag[ks][nf][lane];
            unsigned b0b = __float_as_uint(bv.x), b0s = __float_as_uint(bv.y);
            unsigned b1b = __float_as_uint(bv.z), b1s = __float_as_uint(bv.w);
            asm volatile(
                "mma.sync.aligned.m16n8k8.row.col.f32.tf32.tf32.f32 "
                "{%0,%1,%2,%3}, {%4,%5,%6,%7}, {%8,%9}, {%0,%1,%2,%3};"
                : "+f"(acc[nf][0]), "+f"(acc[nf][1]), "+f"(acc[nf][2]), "+f"(acc[nf][3])
                : "r"(ab0), "r"(ab1), "r"(ab2), "r"(ab3), "r"(b0b), "r"(b1b));
            asm volatile(
                "mma.sync.aligned.m16n8k8.row.col.f32.tf32.tf32.f32 "
                "{%0,%1,%2,%3}, {%4,%5,%6,%7}, {%8,%9}, {%0,%1,%2,%3};"
                : "+f"(acc[nf][0]), "+f"(acc[nf][1]), "+f"(acc[nf][2]), "+f"(acc[nf][3])
                : "r"(ab0), "r"(ab1), "r"(ab2), "r"(ab3), "r"(b0s), "r"(b1s));
            asm volatile(
                "mma.sync.aligned.m16n8k8.row.col.f32.tf32.tf32.f32 "
                "{%0,%1,%2,%3}, {%4,%5,%6,%7}, {%8,%9}, {%0,%1,%2,%3};"
                : "+f"(acc[nf][0]), "+f"(acc[nf][1]), "+f"(acc[nf][2]), "+f"(acc[nf][3])
                : "r"(as0), "r"(as1), "r"(as2), "r"(as3), "r"(b0b), "r"(b1b));
        }
    }

    const float2* hi2 = (const float2*)g_hi;
    const float2* hj2 = (const float2*)g_hj;

    int t = lane & 3;
    int srcA = (lane & 28) | (t >> 1);
    int srcB = srcA | 2;

    float p0 = 0.f, p1 = 0.f;
#pragma unroll
    for (int nf = 0; nf < 4; nf++) {
        int n0 = nf * 8 + t * 2;
        float2 hia = hi2[s0 * 16 + n0 / 2];
        float2 hja = hj2[d0 * 16 + n0 / 2];
        float2 hib = hi2[s1 * 16 + n0 / 2];
        float2 hjb = hj2[d1 * 16 + n0 / 2];
        float v0 = acc[nf][0] + hia.x + hja.x;
        float v1 = acc[nf][1] + hia.y + hja.y;
        float v2 = acc[nf][2] + hib.x + hjb.x;
        float v3 = acc[nf][3] + hib.y + hjb.y;
        v0 = (v0 > 0.f) ? v0 : 0.01f * v0;
        v1 = (v1 > 0.f) ? v1 : 0.01f * v1;
        v2 = (v2 > 0.f) ? v2 : 0.01f * v2;
        v3 = (v3 > 0.f) ? v3 : 0.01f * v3;
        float a0 = As[n0], a1 = As[n0 + 1];
        p0 += v0 * a0 + v1 * a1;
        p1 += v2 * a0 + v3 * a1;

        if (!lastl) {
            // (v0,v1)/(v2,v3) [cols 2t,2t+1] -> a-layout [cols t, t+4]
            float y0 = __shfl_sync(0xffffffffu, v0, srcA);
            float y1 = __shfl_sync(0xffffffffu, v1, srcA);
            float z0 = __shfl_sync(0xffffffffu, v0, srcB);
            float z1 = __shfl_sync(0xffffffffu, v1, srcB);
            float u0r0 = (t & 1) ? y1 : y0;
            float u1r0 = (t & 1) ? z1 : z0;
            float y2 = __shfl_sync(0xffffffffu, v2, srcA);
            float y3 = __shfl_sync(0xffffffffu, v3, srcA);
            float z2 = __shfl_sync(0xffffffffu, v2, srcB);
            float z3 = __shfl_sync(0xffffffffu, v3, srcB);
            float u0r1 = (t & 1) ? y3 : y2;
            float u1r1 = (t & 1) ? z3 : z2;
            fout4[(size_t)tile * 128 + nf * 32 + lane] = make_float4(u0r0, u0r1, u1r0, u1r1);
        }
    }
    p0 += __shfl_xor_sync(0xffffffffu, p0, 1);
    p0 += __shfl_xor_sync(0xffffffffu, p0, 2);
    p1 += __shfl_xor_sync(0xffffffffu, p1, 1);
    p1 += __shfl_xor_sync(0xffffffffu, p1, 2);
    if (t == 0) {
        g_logits[base + r0] = p0;
        g_logits[base + r1] = p1;
    }
}

// ---------------- SortPooling + MLP head ----------------
__global__ void k_head(const float* __restrict__ Wlin, const float* __restrict__ blin,
                       const float* __restrict__ W1, const float* __restrict__ b1,
                       const float* __restrict__ W2, const float* __restrict__ b2,
                       const float* __restrict__ Wc, const float* __restrict__ bc,
                       float* __restrict__ out) {
    __shared__ float sv[256];
    __shared__ int si[256];
    __shared__ int picked[TOPK];
    __shared__ float xs[TOPK * DD];
    __shared__ float y1[32], y2[32], y3[32];
    int tid = threadIdx.x;

    for (int t = 0; t < TOPK; t++) {
        float best = -1e30f;
        int bidx = 0x7fffffff;
        for (int i = tid; i < NN; i += 256) {
            bool skip = false;
            for (int p = 0; p < t; p++)
                if (picked[p] == i) skip = true;
            if (skip) continue;
            float v = g_rowmax[i];
            if (v > best || (v == best && i < bidx)) { best = v; bidx = i; }
        }
        sv[tid] = best;
        si[tid] = bidx;
        __syncthreads();
        for (int off = 128; off; off >>= 1) {
            if (tid < off) {
                float v2 = sv[tid + off];
                int i2 = si[tid + off];
                if (v2 > sv[tid] || (v2 == sv[tid] && i2 < si[tid])) {
                    sv[tid] = v2;
                    si[tid] = i2;
                }
            }
            __syncthreads();
        }
        if (tid == 0) picked[t] = si[0];
        __syncthreads();
    }

    if (tid < TOPK) {
        float r[32];
        int n = picked[tid];
        for (int d = 0; d < 32; d++) r[d] = g_h[n * DD + d];
        for (int a = 1; a < 32; a++) {
            float key = r[a];
            int b = a - 1;
            while (b >= 0 && r[b] > key) { r[b + 1] = r[b]; b--; }
            r[b + 1] = key;
        }
        for (int d = 0; d < 32; d++) xs[tid * 32 + d] = r[d];
    }
    __syncthreads();

    if (tid < 32) {
        float a = blin[tid];
        for (int i = 0; i < 256; i++) a += xs[i] * Wlin[i * 32 + tid];
        y1[tid] = fmaxf(a, 0.f);
    }
    __syncthreads();
    if (tid < 32) {
        float a = b1[tid];
        for (int k = 0; k < 32; k++) a += y1[k] * W1[k * 32 + tid];
        y2[tid] = fmaxf(a, 0.f);
    }
    __syncthreads();
    if (tid < 32) {
        float a = b2[tid];
        for (int k = 0; k < 32; k++) a += y2[k] * W2[k * 32 + tid];
        y3[tid] = fmaxf(a, 0.f);
    }
    __syncthreads();
    if (tid < 2) {
        float a = bc[tid];
        for (int k = 0; k < 32; k++) a += y3[k] * Wc[k * 2 + tid];
        out[tid] = a;
    }
}

// ---------------- launch ----------------
extern "C" void kernel_launch(void* const* d_in, const int* in_sizes, int n_in,
                              void* d_out, int out_size) {
    (void)in_sizes; (void)n_in; (void)out_size;
    const int*   h_tok     = (const int*)d_in[0];
    const int*   e_tok     = (const int*)d_in[1];
    const int*   src       = (const int*)d_in[2];
    const int*   dst       = (const int*)d_in[3];
    const float* tok_emb   = (const float*)d_in[4];
    const float* e_tok_emb = (const float*)d_in[5];
    const float* W_ni      = (const float*)d_in[6];
    const float* W_nj      = (const float*)d_in[7];
    const float* W_fij     = (const float*)d_in[8];
    const float* b_edge    = (const float*)d_in[9];
    const float* attn      = (const float*)d_in[10];
    const float* W_node    = (const float*)d_in[11];
    const float* W_lin     = (const float*)d_in[12];
    const float* b_lin     = (const float*)d_in[13];
    const float* W1        = (const float*)d_in[14];
    const float* b1        = (const float*)d_in[15];
    const float* W2        = (const float*)d_in[16];
    const float* b2        = (const float*)d_in[17];
    const float* Wc        = (const float*)d_in[18];
    const float* bc        = (const float*)d_in[19];
    float* out = (float*)d_out;

    const int EB = (EE + 255) / 256;          // 6250
    const int WB = (NN + 7) / 8;              // 6250
    const int MB = (EE + 127) / 128;          // 12500

    k_hist<<<EB, 256>>>(dst);
    k_scan<<<1, 1024>>>();
    k_scatter<<<EB, 256>>>(dst);
    k_gather<<<EB, 256>>>(src, dst, e_tok);
    k_init_proj<<<WB, 256>>>(h_tok, tok_emb, W_ni, W_nj, W_node, b_edge);

    for (int l = 0; l < NLAYERS; l++) {
        int flags = (l & 1) | ((l == 0) ? 2 : 0) | ((l == NLAYERS - 1) ? 4 : 0);
        k_edge_mma<<<MB, 256>>>(W_fij + l * 1024, attn + l * 32, e_tok_emb, flags);
        if (l < NLAYERS - 1) {
            k_aggproj<<<WB, 256>>>(W_ni + (l + 1) * 1024, W_nj + (l + 1) * 1024,
                                   W_node + (l + 1) * 1024, b_edge + (l + 1) * 32, 0);
        } else {
            k_aggproj<<<WB, 256>>>(W_ni, W_nj, W_node, b_edge, 1);
        }
    }

    k_head<<<1, 256>>>(W_lin, b_lin, W1, b1, W2, b2, Wc, bc, out);
}

// round 5
// speedup vs baseline: 1.6538x; 1.0906x over previous
#include <cuda_runtime.h>
#include <cuda_bf16.h>

#define NN 50000
#define EE 1600000
#define DD 32
#define NLAYERS 8
#define TOPK 8
#define VOCAB 100

// ---------------- device scratch (static, no allocations) ----------------
__device__ float g_h [NN*DD];
__device__ float g_hi[NN*DD];
__device__ float g_hj[NN*DD];
__device__ float g_hn[NN*DD];
// e/f in MMA A-fragment tiled layout:
// tile = edge/16 ; float4 F4[tile][4(ks)][32(lane)]
// F4[ks][lane] = { e[r0][ks*8+c0], e[r1][ks*8+c0], e[r0][ks*8+c0+4], e[r1][ks*8+c0+4] }
//   r0 = lane>>2, r1 = r0+8, c0 = lane&3
__device__ float g_e [EE*DD];
__device__ float g_f [EE*DD];
__device__ float g_logits[EE];
__device__ int   g_srcS[EE];
__device__ int   g_dstS[EE];
__device__ int   g_etokS[EE];
__device__ int   g_hist[NN];       // static zero-init; re-zeroed by k_scan each call
__device__ int   g_row [NN+1];
__device__ int   g_cursor[NN];
__device__ float g_rowmax[NN];

__device__ __forceinline__ unsigned f2tf32(float x) {
    unsigned r;
    asm("cvt.rna.tf32.f32 %0, %1;" : "=r"(r) : "f"(x));
    return r;
}

#define EB 6250   // edge blocks (256 thr)
#define WB 6250   // node warp-blocks (8 nodes per 256-thr block)

// ---------------- launch 1: hist (blocks 0..EB-1) + init_proj (blocks EB..) --
__global__ void k_hist_init(const int* __restrict__ dst,
                            const int* __restrict__ h_tok, const float* __restrict__ tok_emb,
                            const float* __restrict__ Wni, const float* __restrict__ Wnj,
                            const float* __restrict__ Wn, const float* __restrict__ b) {
    if (blockIdx.x < EB) {
        int i = blockIdx.x * 256 + threadIdx.x;
        if (i < EE) atomicAdd(&g_hist[dst[i]], 1);
        return;
    }
    __shared__ float wi[32][32], wj[32][32], wn[32][32], bs[32];
    int tid = threadIdx.x;
    for (int i = tid; i < 1024; i += 256) {
        wi[i >> 5][i & 31] = Wni[i];
        wj[i >> 5][i & 31] = Wnj[i];
        wn[i >> 5][i & 31] = Wn[i];
    }
    if (tid < 32) bs[tid] = b[tid];
    __syncthreads();
    int node = (blockIdx.x - EB) * 8 + (tid >> 5);
    int lane = tid & 31;
    if (node >= NN) return;
    float hv = fmaxf(tok_emb[h_tok[node] * DD + lane], 0.f);
    float ai = bs[lane], aj = 0.f, an = 0.f;
#pragma unroll
    for (int k = 0; k < 32; k++) {
        float hk = __shfl_sync(0xffffffffu, hv, k);
        ai += hk * wi[k][lane];
        aj += hk * wj[k][lane];
        an += hk * wn[k][lane];
    }
    g_hi[node * DD + lane] = ai;
    g_hj[node * DD + lane] = aj;
    g_hn[node * DD + lane] = an;
}

// ---------------- launch 2: scan ----------------
__global__ void k_scan() {
    __shared__ int sm[1024];
    int t = threadIdx.x;
    const int CH = (NN + 1023) / 1024;
    int b0 = t * CH;
    int b1 = min(b0 + CH, NN);
    int sum = 0;
    for (int i = b0; i < b1; i++) sum += g_hist[i];
    sm[t] = sum;
    __syncthreads();
    for (int off = 1; off < 1024; off <<= 1) {
        int v = (t >= off) ? sm[t - off] : 0;
        __syncthreads();
        sm[t] += v;
        __syncthreads();
    }
    int pre = sm[t] - sum;
    for (int i = b0; i < b1; i++) {
        g_row[i] = pre;
        g_cursor[i] = pre;
        pre += g_hist[i];
        g_hist[i] = 0;            // re-zero for next call
    }
    if (t == 1023) g_row[NN] = sm[1023];
}

// ---------------- launch 3: fused scatter+gather ----------------
__global__ void k_scatter_gather(const int* __restrict__ src, const int* __restrict__ dst,
                                 const int* __restrict__ e_tok) {
    int i = blockIdx.x * blockDim.x + threadIdx.x;
    if (i >= EE) return;
    int d = dst[i];
    int p = atomicAdd(&g_cursor[d], 1);
    g_srcS[p] = src[i];
    g_dstS[p] = d;
    g_etokS[p] = e_tok[i];
}

// ---------------- launch 4 (PROFILED): edge kernel (tensor core, 3xTF32) ----
// flags: bit0 = swap (read g_f/write g_e), bit1 = first (e from token table), bit2 = last (skip f store)
// dynamic smem: [0, 8192) bfrag float4[4][4][32]; [8192, 8320) As; layer0: etab[VOCAB*33]
__global__ void k_edge_mma(const float* __restrict__ Wf, const float* __restrict__ attn,
                           const float* __restrict__ e_emb, int flags) {
    extern __shared__ float4 dsm[];
    float4* bfragP = dsm;                    // ks*128 + nf*32 + lane
    float*  As     = (float*)(dsm + 512);    // 32 floats
    float*  etab   = As + 32;                // VOCAB*33 floats (layer 0 only)
    const int swap = flags & 1, first = flags & 2, lastl = flags & 4;
    int tid = threadIdx.x;
#pragma unroll
    for (int e2 = 0; e2 < 2; e2++) {
        int eid = tid + e2 * 256;
        int ks = eid >> 7, nf = (eid >> 5) & 3, ln = eid & 31;
        int k0 = ks * 8 + (ln & 3);
        int n  = nf * 8 + (ln >> 2);
        float b0 = Wf[k0 * 32 + n];
        float b1 = Wf[(k0 + 4) * 32 + n];
        unsigned b0b = f2tf32(b0);
        unsigned b0s = f2tf32(b0 - __uint_as_float(b0b));
        unsigned b1b = f2tf32(b1);
        unsigned b1s = f2tf32(b1 - __uint_as_float(b1b));
        bfragP[ks * 128 + nf * 32 + ln] =
            make_float4(__uint_as_float(b0b), __uint_as_float(b0s),
                        __uint_as_float(b1b), __uint_as_float(b1s));
    }
    if (tid < 32) As[tid] = attn[tid];
    if (first) {
        for (int i = tid; i < VOCAB * DD; i += 256)
            etab[(i >> 5) * 33 + (i & 31)] = e_emb[i];
    }
    __syncthreads();

    int warp = tid >> 5;
    int lane = tid & 31;
    int base = (blockIdx.x * 8 + warp) * 16;
    if (base >= EE) return;
    int tile = base >> 4;

    const float4* ein4 = (const float4*)(swap ? g_f : g_e);
    float4*       fout4 = (float4*)(swap ? g_e : g_f);

    int r0 = lane >> 2;
    int r1 = r0 + 8;
    int c0 = lane & 3;

    int s0 = g_srcS[base + r0], s1 = g_srcS[base + r1];
    int d0 = g_dstS[base + r0], d1 = g_dstS[base + r1];
    int t0 = 0, t1 = 0;
    if (first) { t0 = g_etokS[base + r0] * 33; t1 = g_etokS[base + r1] * 33; }

    float acc[4][4];
#pragma unroll
    for (int nf = 0; nf < 4; nf++)
#pragma unroll
        for (int q = 0; q < 4; q++) acc[nf][q] = 0.f;

#pragma unroll
    for (int ks = 0; ks < 4; ks++) {
        float4 va;
        if (first) {
            va.x = etab[t0 + ks * 8 + c0];
            va.y = etab[t1 + ks * 8 + c0];
            va.z = etab[t0 + ks * 8 + c0 + 4];
            va.w = etab[t1 + ks * 8 + c0 + 4];
        } else {
            va = ein4[(size_t)tile * 128 + ks * 32 + lane];
        }
        unsigned ab0 = f2tf32(va.x), ab1 = f2tf32(va.y), ab2 = f2tf32(va.z), ab3 = f2tf32(va.w);
        unsigned as0 = f2tf32(va.x - __uint_as_float(ab0));
        unsigned as1 = f2tf32(va.y - __uint_as_float(ab1));
        unsigned as2 = f2tf32(va.z - __uint_as_float(ab2));
        unsigned as3 = f2tf32(va.w - __uint_as_float(ab3));
#pragma unroll
        for (int nf = 0; nf < 4; nf++) {
            float4 bv = bfragP[ks * 128 + nf * 32 + lane];
            unsigned b0b = __float_as_uint(bv.x), b0s = __float_as_uint(bv.y);
            unsigned b1b = __float_as_uint(bv.z), b1s = __float_as_uint(bv.w);
            asm volatile(
                "mma.sync.aligned.m16n8k8.row.col.f32.tf32.tf32.f32 "
                "{%0,%1,%2,%3}, {%4,%5,%6,%7}, {%8,%9}, {%0,%1,%2,%3};"
                : "+f"(acc[nf][0]), "+f"(acc[nf][1]), "+f"(acc[nf][2]), "+f"(acc[nf][3])
                : "r"(ab0), "r"(ab1), "r"(ab2), "r"(ab3), "r"(b0b), "r"(b1b));
            asm volatile(
                "mma.sync.aligned.m16n8k8.row.col.f32.tf32.tf32.f32 "
                "{%0,%1,%2,%3}, {%4,%5,%6,%7}, {%8,%9}, {%0,%1,%2,%3};"
                : "+f"(acc[nf][0]), "+f"(acc[nf][1]), "+f"(acc[nf][2]), "+f"(acc[nf][3])
                : "r"(ab0), "r"(ab1), "r"(ab2), "r"(ab3), "r"(b0s), "r"(b1s));
            asm volatile(
                "mma.sync.aligned.m16n8k8.row.col.f32.tf32.tf32.f32 "
                "{%0,%1,%2,%3}, {%4,%5,%6,%7}, {%8,%9}, {%0,%1,%2,%3};"
                : "+f"(acc[nf][0]), "+f"(acc[nf][1]), "+f"(acc[nf][2]), "+f"(acc[nf][3])
                : "r"(as0), "r"(as1), "r"(as2), "r"(as3), "r"(b0b), "r"(b1b));
        }
    }

    const float2* hi2 = (const float2*)g_hi;
    const float2* hj2 = (const float2*)g_hj;
    int t = lane & 3;
    int srcA = (lane & 28) | (t >> 1);
    int srcB = srcA | 2;

    // batched epilogue loads (issued before any store -> high MLP)
    float2 hia[4], hja[4], hib[4], hjb[4];
#pragma unroll
    for (int nf = 0; nf < 4; nf++) {
        hia[nf] = hi2[s0 * 16 + nf * 4 + t];
        hja[nf] = hj2[d0 * 16 + nf * 4 + t];
        hib[nf] = hi2[s1 * 16 + nf * 4 + t];
        hjb[nf] = hj2[d1 * 16 + nf * 4 + t];
    }

    float p0 = 0.f, p1 = 0.f;
#pragma unroll
    for (int nf = 0; nf < 4; nf++) {
        int n0 = nf * 8 + t * 2;
        float v0 = acc[nf][0] + hia[nf].x + hja[nf].x;
        float v1 = acc[nf][1] + hia[nf].y + hja[nf].y;
        float v2 = acc[nf][2] + hib[nf].x + hjb[nf].x;
        float v3 = acc[nf][3] + hib[nf].y + hjb[nf].y;
        v0 = (v0 > 0.f) ? v0 : 0.01f * v0;
        v1 = (v1 > 0.f) ? v1 : 0.01f * v1;
        v2 = (v2 > 0.f) ? v2 : 0.01f * v2;
        v3 = (v3 > 0.f) ? v3 : 0.01f * v3;
        float a0 = As[n0], a1 = As[n0 + 1];
        p0 += v0 * a0 + v1 * a1;
        p1 += v2 * a0 + v3 * a1;

        if (!lastl) {
            // (v0,v1)/(v2,v3) [cols 2t,2t+1] -> a-layout [cols t, t+4]
            float y0 = __shfl_sync(0xffffffffu, v0, srcA);
            float y1 = __shfl_sync(0xffffffffu, v1, srcA);
            float z0 = __shfl_sync(0xffffffffu, v0, srcB);
            float z1 = __shfl_sync(0xffffffffu, v1, srcB);
            float u0r0 = (t & 1) ? y1 : y0;
            float u1r0 = (t & 1) ? z1 : z0;
            float y2 = __shfl_sync(0xffffffffu, v2, srcA);
            float y3 = __shfl_sync(0xffffffffu, v3, srcA);
            float z2 = __shfl_sync(0xffffffffu, v2, srcB);
            float z3 = __shfl_sync(0xffffffffu, v3, srcB);
            float u0r1 = (t & 1) ? y3 : y2;
            float u1r1 = (t & 1) ? z3 : z2;
            fout4[(size_t)tile * 128 + nf * 32 + lane] = make_float4(u0r0, u0r1, u1r0, u1r1);
        }
    }
    p0 += __shfl_xor_sync(0xffffffffu, p0, 1);
    p0 += __shfl_xor_sync(0xffffffffu, p0, 2);
    p1 += __shfl_xor_sync(0xffffffffu, p1, 1);
    p1 += __shfl_xor_sync(0xffffffffu, p1, 2);
    if (t == 0) {
        g_logits[base + r0] = p0;
        g_logits[base + r1] = p1;
    }
}

// ---------------- agg (+relu) fused with next layer's projections ----------
__global__ void k_aggproj(const float* __restrict__ Wni, const float* __restrict__ Wnj,
                          const float* __restrict__ Wn, const float* __restrict__ b,
                          int last) {
    __shared__ float wi[32][32], wj[32][32], wn[32][32], bs[32];
    int tid = threadIdx.x;
    if (!last) {
        for (int i = tid; i < 1024; i += 256) {
            wi[i >> 5][i & 31] = Wni[i];
            wj[i >> 5][i & 31] = Wnj[i];
            wn[i >> 5][i & 31] = Wn[i];
        }
        if (tid < 32) bs[tid] = b[tid];
    }
    __syncthreads();
    int node = blockIdx.x * 8 + (tid >> 5);
    int lane = tid & 31;
    if (node >= NN) return;
    int beg = g_row[node], end = g_row[node + 1];
    float m = -1e30f;
    for (int i = beg + lane; i < end; i += 32) m = fmaxf(m, g_logits[i]);
#pragma unroll
    for (int o = 16; o; o >>= 1) m = fmaxf(m, __shfl_xor_sync(0xffffffffu, m, o));
    float s = 0.f, acc = 0.f;
    for (int chunk = beg; chunk < end; chunk += 32) {
        int i = chunk + lane;
        float w = 0.f;
        int sv = 0;
        if (i < end) {
            w = __expf(g_logits[i] - m);
            sv = g_srcS[i];
        }
        s += w;
#pragma unroll
        for (int e = 0; e < 32; e++) {
            float we = __shfl_sync(0xffffffffu, w, e);
            int se = __shfl_sync(0xffffffffu, sv, e);
            acc += we * g_hn[se * DD + lane];
        }
    }
#pragma unroll
    for (int o = 16; o; o >>= 1) s += __shfl_xor_sync(0xffffffffu, s, o);
    float hv = (end > beg) ? fmaxf(acc / s, 0.f) : 0.f;

    if (last) {
        g_h[node * DD + lane] = hv;
        float v = hv;
#pragma unroll
        for (int o = 16; o; o >>= 1) v = fmaxf(v, __shfl_xor_sync(0xffffffffu, v, o));
        if (lane == 0) g_rowmax[node] = v;
    } else {
        float ai = bs[lane], aj = 0.f, an = 0.f;
#pragma unroll
        for (int k = 0; k < 32; k++) {
            float hk = __shfl_sync(0xffffffffu, hv, k);
            ai += hk * wi[k][lane];
            aj += hk * wj[k][lane];
            an += hk * wn[k][lane];
        }
        g_hi[node * DD + lane] = ai;
        g_hj[node * DD + lane] = aj;
        g_hn[node * DD + lane] = an;
    }
}

// ---------------- SortPooling + MLP head ----------------
__global__ void k_head(const float* __restrict__ Wlin, const float* __restrict__ blin,
                       const float* __restrict__ W1, const float* __restrict__ b1,
                       const float* __restrict__ W2, const float* __restrict__ b2,
                       const float* __restrict__ Wc, const float* __restrict__ bc,
                       float* __restrict__ out) {
    __shared__ float sv[256];
    __shared__ int si[256];
    __shared__ int picked[TOPK];
    __shared__ float xs[TOPK * DD];
    __shared__ float y1[32], y2[32], y3[32];
    int tid = threadIdx.x;

    for (int t = 0; t < TOPK; t++) {
        float best = -1e30f;
        int bidx = 0x7fffffff;
        for (int i = tid; i < NN; i += 256) {
            bool skip = false;
            for (int p = 0; p < t; p++)
                if (picked[p] == i) skip = true;
            if (skip) continue;
            float v = g_rowmax[i];
            if (v > best || (v == best && i < bidx)) { best = v; bidx = i; }
        }
        sv[tid] = best;
        si[tid] = bidx;
        __syncthreads();
        for (int off = 128; off; off >>= 1) {
            if (tid < off) {
                float v2 = sv[tid + off];
                int i2 = si[tid + off];
                if (v2 > sv[tid] || (v2 == sv[tid] && i2 < si[tid])) {
                    sv[tid] = v2;
                    si[tid] = i2;
                }
            }
            __syncthreads();
        }
        if (tid == 0) picked[t] = si[0];
        __syncthreads();
    }

    if (tid < TOPK) {
        float r[32];
        int n = picked[tid];
        for (int d = 0; d < 32; d++) r[d] = g_h[n * DD + d];
        for (int a = 1; a < 32; a++) {
            float key = r[a];
            int b = a - 1;
            while (b >= 0 && r[b] > key) { r[b + 1] = r[b]; b--; }
            r[b + 1] = key;
        }
        for (int d = 0; d < 32; d++) xs[tid * 32 + d] = r[d];
    }
    __syncthreads();

    if (tid < 32) {
        float a = blin[tid];
        for (int i = 0; i < 256; i++) a += xs[i] * Wlin[i * 32 + tid];
        y1[tid] = fmaxf(a, 0.f);
    }
    __syncthreads();
    if (tid < 32) {
        float a = b1[tid];
        for (int k = 0; k < 32; k++) a += y1[k] * W1[k * 32 + tid];
        y2[tid] = fmaxf(a, 0.f);
    }
    __syncthreads();
    if (tid < 32) {
        float a = b2[tid];
        for (int k = 0; k < 32; k++) a += y2[k] * W2[k * 32 + tid];
        y3[tid] = fmaxf(a, 0.f);
    }
    __syncthreads();
    if (tid < 2) {
        float a = bc[tid];
        for (int k = 0; k < 32; k++) a += y3[k] * Wc[k * 2 + tid];
        out[tid] = a;
    }
}

// ---------------- launch ----------------
extern "C" void kernel_launch(void* const* d_in, const int* in_sizes, int n_in,
                              void* d_out, int out_size) {
    (void)in_sizes; (void)n_in; (void)out_size;
    const int*   h_tok     = (const int*)d_in[0];
    const int*   e_tok     = (const int*)d_in[1];
    const int*   src       = (const int*)d_in[2];
    const int*   dst       = (const int*)d_in[3];
    const float* tok_emb   = (const float*)d_in[4];
    const float* e_tok_emb = (const float*)d_in[5];
    const float* W_ni      = (const float*)d_in[6];
    const float* W_nj      = (const float*)d_in[7];
    const float* W_fij     = (const float*)d_in[8];
    const float* b_edge    = (const float*)d_in[9];
    const float* attn      = (const float*)d_in[10];
    const float* W_node    = (const float*)d_in[11];
    const float* W_lin     = (const float*)d_in[12];
    const float* b_lin     = (const float*)d_in[13];
    const float* W1        = (const float*)d_in[14];
    const float* b1        = (const float*)d_in[15];
    const float* W2        = (const float*)d_in[16];
    const float* b2        = (const float*)d_in[17];
    const float* Wc        = (const float*)d_in[18];
    const float* bc        = (const float*)d_in[19];
    float* out = (float*)d_out;

    const int MB = (EE + 127) / 128;          // 12500
    const size_t SM_BASE  = 512 * 16 + 32 * 4;            // 8320
    const size_t SM_FIRST = SM_BASE + VOCAB * 33 * 4;     // 21520

    // launches 1..3 (setup), launch 4 = edge layer0 (ncu-profiled)
    k_hist_init<<<EB + WB, 256>>>(dst, h_tok, tok_emb, W_ni, W_nj, W_node, b_edge);
    k_scan<<<1, 1024>>>();
    k_scatter_gather<<<EB, 256>>>(src, dst, e_tok);

    for (int l = 0; l < NLAYERS; l++) {
        int flags = (l & 1) | ((l == 0) ? 2 : 0) | ((l == NLAYERS - 1) ? 4 : 0);
        k_edge_mma<<<MB, 256, (l == 0) ? SM_FIRST : SM_BASE>>>(
            W_fij + l * 1024, attn + l * 32, e_tok_emb, flags);
        if (l < NLAYERS - 1) {
            k_aggproj<<<WB, 256>>>(W_ni + (l + 1) * 1024, W_nj + (l + 1) * 1024,
                                   W_node + (l + 1) * 1024, b_edge + (l + 1) * 32, 0);
        } else {
            k_aggproj<<<WB, 256>>>(W_ni, W_nj, W_node, b_edge, 1);
        }
    }

    k_head<<<1, 256>>>(W_lin, b_lin, W1, b1, W2, b2, Wc, bc, out);
}